// round 6
// baseline (speedup 1.0000x reference)
#include <cuda_runtime.h>
#include <cuda_fp16.h>
#include <stdint.h>
#include <stddef.h>

#define N_ROWS 8192
#define N_COLS 8192
#define DD     1024

// Scratch (no cudaMalloc allowed): 134 MB fp16 weight matrix, row sums, fp16 x.
static __device__ __half g_E[(size_t)N_ROWS * N_COLS];
static __device__ float  g_S[N_ROWS];
static __device__ __half g_Xh[(size_t)N_ROWS * DD];

// ---------------------------------------------------------------------------
// Threefry-2x32 (20 rounds) with key = jax.random.key(42) -> (k1=0, k2=42)
// ---------------------------------------------------------------------------
__device__ __forceinline__ uint32_t rotl32(uint32_t x, int d) {
    return __funnelshift_l(x, x, d);
}

__device__ __forceinline__ void threefry_0_42(uint32_t x0, uint32_t x1,
                                              uint32_t& o0, uint32_t& o1) {
    const uint32_t ks0 = 0u;
    const uint32_t ks1 = 42u;
    const uint32_t ks2 = 0x1BD11BDAu ^ 0u ^ 42u;  // 0x1BD11BF0
    x0 += ks0; x1 += ks1;
#define TF_R(r) { x0 += x1; x1 = rotl32(x1, (r)); x1 ^= x0; }
    TF_R(13) TF_R(15) TF_R(26) TF_R(6)
    x0 += ks1; x1 += ks2 + 1u;
    TF_R(17) TF_R(29) TF_R(16) TF_R(24)
    x0 += ks2; x1 += ks0 + 2u;
    TF_R(13) TF_R(15) TF_R(26) TF_R(6)
    x0 += ks0; x1 += ks1 + 3u;
    TF_R(17) TF_R(29) TF_R(16) TF_R(24)
    x0 += ks1; x1 += ks2 + 4u;
    TF_R(13) TF_R(15) TF_R(26) TF_R(6)
    x0 += ks2; x1 += ks0 + 5u;
#undef TF_R
    o0 = x0; o1 = x1;
}

// ---------------------------------------------------------------------------
// XLA's f32 ErfInv (Giles single-precision rational polynomial) — we must
// match the REFERENCE's approximation, not the true erfinv. CUDA's erfinvf
// deviates from this polynomial exactly in the extreme tail, where the
// softmax's dominant weights live.
// ---------------------------------------------------------------------------
__device__ __forceinline__ float erfinv_xla(float x) {
    float w = -log1pf(-x * x);
    float p;
    if (w < 5.0f) {
        w -= 2.5f;
        p = 2.81022636e-08f;
        p = fmaf(p, w, 3.43273939e-07f);
        p = fmaf(p, w, -3.5233877e-06f);
        p = fmaf(p, w, -4.39150654e-06f);
        p = fmaf(p, w, 0.00021858087f);
        p = fmaf(p, w, -0.00125372503f);
        p = fmaf(p, w, -0.00417768164f);
        p = fmaf(p, w, 0.246640727f);
        p = fmaf(p, w, 1.50140941f);
    } else {
        w = sqrtf(w) - 3.0f;
        p = -0.000200214257f;
        p = fmaf(p, w, 0.000100950558f);
        p = fmaf(p, w, 0.00134934322f);
        p = fmaf(p, w, -0.00367342844f);
        p = fmaf(p, w, 0.00573950773f);
        p = fmaf(p, w, -0.0076224613f);
        p = fmaf(p, w, 0.00943887047f);
        p = fmaf(p, w, 1.00167406f);
        p = fmaf(p, w, 2.83297682f);
    }
    return p * x;
}

// ---------------------------------------------------------------------------
// Pass 0: x (f32) -> fp16
// ---------------------------------------------------------------------------
__global__ void convert_x_kernel(const float* __restrict__ x) {
    int idx = blockIdx.x * 1024 + threadIdx.x;   // grid 8192 x 1024 = N_ROWS*DD
    g_Xh[idx] = __float2half_rn(x[idx]);
}

// ---------------------------------------------------------------------------
// Pass 1: generate E[i][j] = exp(2*m_ij) * 2^-4 (fp16) and row sums S[i] (f32)
// m_ij = sqrt(2)*erfinv_xla(u), u from JAX partitionable threefry bits:
//   per element t: counter = (hi(t)=0, lo(t)=t), bits = o0 XOR o1
// ---------------------------------------------------------------------------
__global__ __launch_bounds__(1024)
void gen_kernel() {
    const int i   = blockIdx.x;       // row
    const int tid = threadIdx.x;      // 0..1023
    const size_t rowbase = (size_t)i * N_COLS;

    float s = 0.0f;
#pragma unroll
    for (int k = 0; k < 8; k++) {
        uint32_t j = (uint32_t)tid + (uint32_t)k * 1024u;
        uint32_t t = (uint32_t)rowbase + j;        // < 2^26, hi word = 0
        uint32_t o0, o1;
        threefry_0_42(0u, t, o0, o1);
        uint32_t bits = o0 ^ o1;                   // partitionable 32-bit combine

        // jax uniform(lo=nextafter(-1,0), hi=1) for f32:
        // f in [0,1); scale (hi-lo) rounds to exactly 2.0f; mul by 2 exact,
        // single rounding in the add -> bit-identical to XLA.
        float f = __uint_as_float((bits >> 9) | 0x3f800000u) - 1.0f;
        float u = f * 2.0f + -0.99999994f;
        u = fmaxf(u, -0.99999994f);

        float m = 1.41421354f * erfinv_xla(u);     // float32(sqrt(2)) * erf_inv
        // exp(2m) = 2^(m * 2/ln2)
        float e = exp2f(m * 2.8853900817779268f);
        s += e;
        g_E[rowbase + j] = __float2half_rn(e * 0.0625f);  // 2^-4 anti-overflow
    }

    // block reduce row sum (1024 threads = 32 warps)
    __shared__ float red[32];
#pragma unroll
    for (int o = 16; o > 0; o >>= 1) s += __shfl_xor_sync(0xffffffffu, s, o);
    if ((tid & 31) == 0) red[tid >> 5] = s;
    __syncthreads();
    if (tid < 32) {
        float v = red[tid];
#pragma unroll
        for (int o = 16; o > 0; o >>= 1) v += __shfl_xor_sync(0xffffffffu, v, o);
        if (tid == 0) g_S[i] = v;
    }
}

// ---------------------------------------------------------------------------
// Pass 2: out[i,:] = (16/S[i]) * sum_j E[i][j] * Xh[j][:]
// fp16 mma.sync m16n8k16 GEMM, BM=128 BN=128 BK=32, 2-stage cp.async pipeline.
// ---------------------------------------------------------------------------
#define BM 128
#define BN 128
#define BK 32
#define SA_LD 40    // 32 + 8 halfs  (80B rows -> conflict-reduced ldmatrix)
#define SB_LD 136   // 128 + 8 halfs (272B rows)

__device__ __forceinline__ void cp_async16(void* smem, const void* gmem) {
    uint32_t s = (uint32_t)__cvta_generic_to_shared(smem);
    asm volatile("cp.async.cg.shared.global [%0], [%1], 16;\n" :: "r"(s), "l"(gmem));
}

__global__ __launch_bounds__(256, 2)
void gemm_kernel(float* __restrict__ out) {
    __shared__ __half sA[2][BM][SA_LD];
    __shared__ __half sB[2][BK][SB_LD];

    const int tid  = threadIdx.x;
    const int wid  = tid >> 5;
    const int lane = tid & 31;
    const int wm   = wid & 3;   // warp row  (4) -> 32 rows each
    const int wn   = wid >> 2;  // warp col  (2) -> 64 cols each
    const int bm0  = blockIdx.y * BM;
    const int bn0  = blockIdx.x * BN;

    float acc[2][8][4];
#pragma unroll
    for (int a = 0; a < 2; a++)
#pragma unroll
        for (int b = 0; b < 8; b++)
#pragma unroll
            for (int c = 0; c < 4; c++) acc[a][b][c] = 0.0f;

    // per-thread load coordinates
    const int aR = tid >> 2, aC = (tid & 3) * 8;    // A: 64 rows x 4 chunks / 256 thr
    const int bR = tid >> 4, bC = (tid & 15) * 8;   // B: 16 rows x 16 chunks

#define LOAD_TILES(st, k0)                                                          \
    {                                                                               \
        cp_async16(&sA[st][aR][aC],      g_E + (size_t)(bm0 + aR) * N_COLS + (k0) + aC); \
        cp_async16(&sA[st][aR + 64][aC], g_E + (size_t)(bm0 + aR + 64) * N_COLS + (k0) + aC); \
        cp_async16(&sB[st][bR][bC],      g_Xh + (size_t)((k0) + bR) * DD + bn0 + bC);      \
        cp_async16(&sB[st][bR + 16][bC], g_Xh + (size_t)((k0) + bR + 16) * DD + bn0 + bC); \
        asm volatile("cp.async.commit_group;\n");                                   \
    }

    LOAD_TILES(0, 0)

    const int KT = N_COLS / BK;  // 256
    for (int kt = 0; kt < KT; kt++) {
        const int st = kt & 1;
        if (kt + 1 < KT) {
            LOAD_TILES(st ^ 1, (kt + 1) * BK)
            asm volatile("cp.async.wait_group 1;\n");
        } else {
            asm volatile("cp.async.wait_group 0;\n");
        }
        __syncthreads();

#pragma unroll
        for (int kk = 0; kk < 2; kk++) {
            uint32_t a[2][4];
#pragma unroll
            for (int mt = 0; mt < 2; mt++) {
                uint32_t ad = (uint32_t)__cvta_generic_to_shared(
                    &sA[st][wm * 32 + mt * 16 + (lane & 15)][kk * 16 + (lane >> 4) * 8]);
                asm volatile(
                    "ldmatrix.sync.aligned.m8n8.x4.shared.b16 {%0,%1,%2,%3}, [%4];"
                    : "=r"(a[mt][0]), "=r"(a[mt][1]), "=r"(a[mt][2]), "=r"(a[mt][3])
                    : "r"(ad));
            }
#pragma unroll
            for (int nt = 0; nt < 4; nt++) {
                uint32_t b0, b1, b2, b3;
                uint32_t bd = (uint32_t)__cvta_generic_to_shared(
                    &sB[st][kk * 16 + (lane & 15)][wn * 64 + nt * 16 + (lane >> 4) * 8]);
                asm volatile(
                    "ldmatrix.sync.aligned.m8n8.x4.trans.shared.b16 {%0,%1,%2,%3}, [%4];"
                    : "=r"(b0), "=r"(b1), "=r"(b2), "=r"(b3)
                    : "r"(bd));
#pragma unroll
                for (int mt = 0; mt < 2; mt++) {
                    asm volatile(
                        "mma.sync.aligned.m16n8k16.row.col.f32.f16.f16.f32 "
                        "{%0,%1,%2,%3}, {%4,%5,%6,%7}, {%8,%9}, {%0,%1,%2,%3};"
                        : "+f"(acc[mt][2 * nt][0]), "+f"(acc[mt][2 * nt][1]),
                          "+f"(acc[mt][2 * nt][2]), "+f"(acc[mt][2 * nt][3])
                        : "r"(a[mt][0]), "r"(a[mt][1]), "r"(a[mt][2]), "r"(a[mt][3]),
                          "r"(b0), "r"(b1));
                    asm volatile(
                        "mma.sync.aligned.m16n8k16.row.col.f32.f16.f16.f32 "
                        "{%0,%1,%2,%3}, {%4,%5,%6,%7}, {%8,%9}, {%0,%1,%2,%3};"
                        : "+f"(acc[mt][2 * nt + 1][0]), "+f"(acc[mt][2 * nt + 1][1]),
                          "+f"(acc[mt][2 * nt + 1][2]), "+f"(acc[mt][2 * nt + 1][3])
                        : "r"(a[mt][0]), "r"(a[mt][1]), "r"(a[mt][2]), "r"(a[mt][3]),
                          "r"(b2), "r"(b3));
                }
            }
        }
        __syncthreads();
    }

    // epilogue: scale each row by 16/S[row]  (undoes the 2^-4 and normalizes)
#pragma unroll
    for (int mt = 0; mt < 2; mt++) {
        const int r0 = bm0 + wm * 32 + mt * 16 + (lane >> 2);
        const float sc0 = 16.0f / g_S[r0];
        const float sc1 = 16.0f / g_S[r0 + 8];
#pragma unroll
        for (int q = 0; q < 8; q++) {
            const int c0 = bn0 + wn * 64 + q * 8 + (lane & 3) * 2;
            float2 v0 = make_float2(acc[mt][q][0] * sc0, acc[mt][q][1] * sc0);
            float2 v1 = make_float2(acc[mt][q][2] * sc1, acc[mt][q][3] * sc1);
            *(float2*)(out + (size_t)r0 * DD + c0)       = v0;
            *(float2*)(out + (size_t)(r0 + 8) * DD + c0) = v1;
        }
    }
}

#undef LOAD_TILES

// ---------------------------------------------------------------------------
extern "C" void kernel_launch(void* const* d_in, const int* in_sizes, int n_in,
                              void* d_out, int out_size) {
    (void)in_sizes; (void)n_in; (void)out_size;
    const float* x = (const float*)d_in[0];   // [8192, 1024] f32
    // d_in[1] = edge_index: unused by the reference, unused here.
    float* out = (float*)d_out;               // [8192, 1024] f32

    convert_x_kernel<<<N_ROWS, 1024>>>(x);
    gen_kernel<<<N_ROWS, 1024>>>();
    dim3 grid(DD / BN, N_ROWS / BM);          // (8, 64)
    gemm_kernel<<<grid, 256>>>(out);
}

// round 9
// speedup vs baseline: 1.0831x; 1.0831x over previous
#include <cuda_runtime.h>
#include <cuda_fp16.h>
#include <stdint.h>
#include <stddef.h>

#define N_ROWS 8192
#define N_COLS 8192
#define DD     1024

// Scratch (no cudaMalloc allowed)
static __device__ __half g_E[(size_t)N_ROWS * N_COLS];   // weights exp(2m)*2^-4
static __device__ float  g_S[N_ROWS];                    // scaled row sums
static __device__ __half g_Xh[(size_t)N_ROWS * DD];      // x as fp16, row-major [k][n]

// ===========================================================================
// Threefry-2x32 (20 rounds), key = (0, 42); JAX partitionable combine o0^o1
// ===========================================================================
__device__ __forceinline__ uint32_t rotl32(uint32_t x, int d) {
    return __funnelshift_l(x, x, d);
}

__device__ __forceinline__ uint32_t threefry_bits(uint32_t t) {
    uint32_t x0 = 0u, x1 = t;
    const uint32_t ks1 = 42u, ks2 = 0x1BD11BF0u;
    x1 += ks1;
#define TF_R(r) { x0 += x1; x1 = rotl32(x1, (r)); x1 ^= x0; }
    TF_R(13) TF_R(15) TF_R(26) TF_R(6)
    x0 += ks1; x1 += ks2 + 1u;
    TF_R(17) TF_R(29) TF_R(16) TF_R(24)
    x0 += ks2; x1 += 2u;
    TF_R(13) TF_R(15) TF_R(26) TF_R(6)
    x1 += ks1 + 3u;
    TF_R(17) TF_R(29) TF_R(16) TF_R(24)
    x0 += ks1; x1 += ks2 + 4u;
    TF_R(13) TF_R(15) TF_R(26) TF_R(6)
    x0 += ks2; x1 += 5u;
#undef TF_R
    return x0 ^ x1;
}

// weight = exp(2*sqrt(2)*erfinv_xla(u)) * 2^-4 ; erfinv matches XLA's Giles poly
__device__ __forceinline__ float gibbs_weight(uint32_t bits) {
    float f = __uint_as_float((bits >> 9) | 0x3f800000u) - 1.0f;
    float u = f * 2.0f + -0.99999994f;
    u = fmaxf(u, -0.99999994f);

    float y = 1.0f - u * u;
    float l; asm("lg2.approx.ftz.f32 %0, %1;" : "=f"(l) : "f"(y));
    float w = l * -0.6931471805599453f;        // -log(1 - u^2)
    float p;
    if (w < 5.0f) {
        w -= 2.5f;
        p = 2.81022636e-08f;
        p = fmaf(p, w, 3.43273939e-07f);
        p = fmaf(p, w, -3.5233877e-06f);
        p = fmaf(p, w, -4.39150654e-06f);
        p = fmaf(p, w, 0.00021858087f);
        p = fmaf(p, w, -0.00125372503f);
        p = fmaf(p, w, -0.00417768164f);
        p = fmaf(p, w, 0.246640727f);
        p = fmaf(p, w, 1.50140941f);
    } else {
        w = sqrtf(w) - 3.0f;
        p = -0.000200214257f;
        p = fmaf(p, w, 0.000100950558f);
        p = fmaf(p, w, 0.00134934322f);
        p = fmaf(p, w, -0.00367342844f);
        p = fmaf(p, w, 0.00573950773f);
        p = fmaf(p, w, -0.0076224613f);
        p = fmaf(p, w, 0.00943887047f);
        p = fmaf(p, w, 1.00167406f);
        p = fmaf(p, w, 2.83297682f);
    }
    float t = p * u;                            // erfinv_xla(u)
    // exp(2*sqrt(2)*t)*2^-4 = 2^(t * 2*sqrt(2)/ln2 - 4)
    float a = fmaf(t, 4.0805578f, -4.0f);
    float e; asm("ex2.approx.ftz.f32 %0, %1;" : "=f"(e) : "f"(a));
    return e;
}

// ===========================================================================
// Pass 0: x (f32) -> fp16, vectorized
// ===========================================================================
__global__ void convert_x_kernel(const float4* __restrict__ x) {
    int idx = blockIdx.x * 256 + threadIdx.x;   // 2097152 threads, 4 floats each
    float4 v = x[idx];
    __half2 h0 = __floats2half2_rn(v.x, v.y);
    __half2 h1 = __floats2half2_rn(v.z, v.w);
    *(uint2*)(g_Xh + (size_t)idx * 4) = make_uint2(
        *(uint32_t*)&h0, *(uint32_t*)&h1);
}

// ===========================================================================
// Pass 1: E + scaled row sums
// ===========================================================================
__global__ __launch_bounds__(1024)
void gen_kernel() {
    const int i   = blockIdx.x;
    const int tid = threadIdx.x;
    const size_t rowbase = (size_t)i * N_COLS;

    float s = 0.0f;
#pragma unroll
    for (int k = 0; k < 4; k++) {
        uint32_t j = 2u * (uint32_t)tid + (uint32_t)k * 2048u;
        uint32_t t0 = (uint32_t)rowbase + j;
        float e0 = gibbs_weight(threefry_bits(t0));
        float e1 = gibbs_weight(threefry_bits(t0 + 1u));
        s += e0 + e1;
        *(__half2*)(g_E + rowbase + j) = __floats2half2_rn(e0, e1);
    }

    __shared__ float red[32];
#pragma unroll
    for (int o = 16; o > 0; o >>= 1) s += __shfl_xor_sync(0xffffffffu, s, o);
    if ((tid & 31) == 0) red[tid >> 5] = s;
    __syncthreads();
    if (tid < 32) {
        float v = red[tid];
#pragma unroll
        for (int o = 16; o > 0; o >>= 1) v += __shfl_xor_sync(0xffffffffu, v, o);
        if (tid == 0) g_S[i] = v;   // scaled sum: epilogue scale = 1/v
    }
}

// ===========================================================================
// Pass 2: out[i,:] = (1/S[i]) * sum_j E[i][j] * Xh[j][:]
// fp16 mma.sync GEMM: BM=128 BN=256 BK=32, warp tile 64x64, 3-stage cp.async.
// ===========================================================================
#define BM 128
#define BN 256
#define BK 32
#define STAGES 3
#define SA_LD 40    // 32 + 8 halfs
#define SB_LD 264   // 256 + 8 halfs
#define SA_BYTES (BM * SA_LD * 2)
#define SB_BYTES (BK * SB_LD * 2)
#define SMEM_TOTAL (STAGES * (SA_BYTES + SB_BYTES))

__device__ __forceinline__ void cp_async16(void* smem, const void* gmem) {
    uint32_t s = (uint32_t)__cvta_generic_to_shared(smem);
    asm volatile("cp.async.cg.shared.global [%0], [%1], 16;\n" :: "r"(s), "l"(gmem));
}

__global__ __launch_bounds__(256, 1)
void gemm_kernel(float* __restrict__ out) {
    extern __shared__ __half smem[];
    __half (*sA)[BM][SA_LD] = (__half (*)[BM][SA_LD])smem;
    __half (*sB)[BK][SB_LD] = (__half (*)[BK][SB_LD])(smem + STAGES * BM * SA_LD);

    const int tid  = threadIdx.x;
    const int wid  = tid >> 5;
    const int lane = tid & 31;
    const int wm   = wid & 1;    // 2 warp-rows  -> 64 rows each
    const int wn   = wid >> 1;   // 4 warp-cols  -> 64 cols each
    const int bm0  = blockIdx.y * BM;
    const int bn0  = blockIdx.x * BN;

    float acc[4][8][4];
#pragma unroll
    for (int a = 0; a < 4; a++)
#pragma unroll
        for (int b = 0; b < 8; b++)
#pragma unroll
            for (int c = 0; c < 4; c++) acc[a][b][c] = 0.0f;

    // per-thread load coords
    const int aR = tid >> 2, aC = (tid & 3) * 8;   // A: 512 chunks, 2/thread
    const int bR = tid >> 5, bC = (tid & 31) * 8;  // B: 1024 chunks, 4/thread

#define LOAD_TILES(st, k0)                                                                 \
    {                                                                                      \
        cp_async16(&sA[st][aR][aC],      g_E + (size_t)(bm0 + aR) * N_COLS + (k0) + aC);   \
        cp_async16(&sA[st][aR + 64][aC], g_E + (size_t)(bm0 + aR + 64) * N_COLS + (k0) + aC); \
        cp_async16(&sB[st][bR][bC],      g_Xh + (size_t)((k0) + bR) * DD + bn0 + bC);      \
        cp_async16(&sB[st][bR +  8][bC], g_Xh + (size_t)((k0) + bR +  8) * DD + bn0 + bC); \
        cp_async16(&sB[st][bR + 16][bC], g_Xh + (size_t)((k0) + bR + 16) * DD + bn0 + bC); \
        cp_async16(&sB[st][bR + 24][bC], g_Xh + (size_t)((k0) + bR + 24) * DD + bn0 + bC); \
        asm volatile("cp.async.commit_group;\n");                                          \
    }

    LOAD_TILES(0, 0)
    LOAD_TILES(1, BK)

    const int KT = N_COLS / BK;  // 256
    for (int kt = 0; kt < KT; kt++) {
        const int st = kt % STAGES;
        if (kt + 2 < KT) {
            asm volatile("cp.async.wait_group 1;\n");
        } else {
            asm volatile("cp.async.wait_group 0;\n");
        }
        __syncthreads();
        if (kt + 2 < KT) LOAD_TILES((kt + 2) % STAGES, (kt + 2) * BK)

#pragma unroll
        for (int kk = 0; kk < 2; kk++) {
            uint32_t a[4][4];
#pragma unroll
            for (int mt = 0; mt < 4; mt++) {
                uint32_t ad = (uint32_t)__cvta_generic_to_shared(
                    &sA[st][wm * 64 + mt * 16 + (lane & 15)][kk * 16 + (lane >> 4) * 8]);
                asm volatile(
                    "ldmatrix.sync.aligned.m8n8.x4.shared.b16 {%0,%1,%2,%3}, [%4];"
                    : "=r"(a[mt][0]), "=r"(a[mt][1]), "=r"(a[mt][2]), "=r"(a[mt][3])
                    : "r"(ad));
            }
#pragma unroll
            for (int nt = 0; nt < 4; nt++) {
                uint32_t b0, b1, b2, b3;
                uint32_t bd = (uint32_t)__cvta_generic_to_shared(
                    &sB[st][kk * 16 + (lane & 15)][wn * 64 + nt * 16 + (lane >> 4) * 8]);
                asm volatile(
                    "ldmatrix.sync.aligned.m8n8.x4.trans.shared.b16 {%0,%1,%2,%3}, [%4];"
                    : "=r"(b0), "=r"(b1), "=r"(b2), "=r"(b3)
                    : "r"(bd));
#pragma unroll
                for (int mt = 0; mt < 4; mt++) {
                    asm volatile(
                        "mma.sync.aligned.m16n8k16.row.col.f32.f16.f16.f32 "
                        "{%0,%1,%2,%3}, {%4,%5,%6,%7}, {%8,%9}, {%0,%1,%2,%3};"
                        : "+f"(acc[mt][2 * nt][0]), "+f"(acc[mt][2 * nt][1]),
                          "+f"(acc[mt][2 * nt][2]), "+f"(acc[mt][2 * nt][3])
                        : "r"(a[mt][0]), "r"(a[mt][1]), "r"(a[mt][2]), "r"(a[mt][3]),
                          "r"(b0), "r"(b1));
                    asm volatile(
                        "mma.sync.aligned.m16n8k16.row.col.f32.f16.f16.f32 "
                        "{%0,%1,%2,%3}, {%4,%5,%6,%7}, {%8,%9}, {%0,%1,%2,%3};"
                        : "+f"(acc[mt][2 * nt + 1][0]), "+f"(acc[mt][2 * nt + 1][1]),
                          "+f"(acc[mt][2 * nt + 1][2]), "+f"(acc[mt][2 * nt + 1][3])
                        : "r"(a[mt][0]), "r"(a[mt][1]), "r"(a[mt][2]), "r"(a[mt][3]),
                          "r"(b2), "r"(b3));
                }
            }
        }
    }

    // epilogue: scale each row by 1/S[row] (both E and S carry the 2^-4)
#pragma unroll
    for (int mt = 0; mt < 4; mt++) {
        const int r0 = bm0 + wm * 64 + mt * 16 + (lane >> 2);
        const float sc0 = 1.0f / g_S[r0];
        const float sc1 = 1.0f / g_S[r0 + 8];
#pragma unroll
        for (int q = 0; q < 8; q++) {
            const int c0 = bn0 + wn * 64 + q * 8 + (lane & 3) * 2;
            float2 v0 = make_float2(acc[mt][q][0] * sc0, acc[mt][q][1] * sc0);
            float2 v1 = make_float2(acc[mt][q][2] * sc1, acc[mt][q][3] * sc1);
            *(float2*)(out + (size_t)r0 * DD + c0)       = v0;
            *(float2*)(out + (size_t)(r0 + 8) * DD + c0) = v1;
        }
    }
}

#undef LOAD_TILES

// ---------------------------------------------------------------------------
extern "C" void kernel_launch(void* const* d_in, const int* in_sizes, int n_in,
                              void* d_out, int out_size) {
    (void)in_sizes; (void)n_in; (void)out_size;
    const float* x = (const float*)d_in[0];   // [8192, 1024] f32
    // d_in[1] = edge_index: unused by the reference, unused here.
    float* out = (float*)d_out;               // [8192, 1024] f32

    cudaFuncSetAttribute(gemm_kernel,
                         cudaFuncAttributeMaxDynamicSharedMemorySize, SMEM_TOTAL);

    convert_x_kernel<<<(N_ROWS * DD / 4) / 256, 256>>>((const float4*)x);
    gen_kernel<<<N_ROWS, 1024>>>();
    dim3 grid(DD / BN, N_ROWS / BM);          // (4, 64)
    gemm_kernel<<<grid, 256, SMEM_TOTAL>>>(out);
}